// round 1
// baseline (speedup 1.0000x reference)
#include <cuda_runtime.h>
#include <math.h>

#define Bn 4
#define Hn 128
#define Wn 128
#define Cn 128
#define SLICE (Hn*Wn)              // 16384
#define NSLICES (Bn*Cn)            // 512
#define NPOS (Bn*Hn*Wn)            // 65536
#define ATT_SCALE 0.08838834764831845f   // 128^-0.5

// ----------------- scratch (device globals; no allocations) -----------------
__device__ __align__(128) float g_q [NSLICES*SLICE];   // (B,C,H,W)
__device__ __align__(128) float g_xs[NPOS*Cn];         // (B,H,W,C) sampled
__device__ __align__(128) float g_kT[NSLICES*SLICE];   // (B,C,W,H)  (transposed!)
__device__ __align__(128) float g_v [NSLICES*SLICE];   // (B,C,H,W)
__device__ __align__(128) float g_ao[NSLICES*SLICE];   // attention out (B,C,H,W)
__device__ __align__(128) float g_coords[NPOS*2];      // (xg, yg) pixel coords
__device__ __align__(128) float g_WqT[Cn*Cn];
__device__ __align__(128) float g_WkT[Cn*Cn];
__device__ __align__(128) float g_WvT[Cn*Cn];
__device__ __align__(128) float g_WoT[Cn*Cn];
__device__ __align__(128) float g_Weff[2*Cn*25];       // folded Wc2 @ Wc1
__device__ __align__(128) float g_beff[2];

extern __shared__ float smem[];

// ----------------- prep: weight transposes + conv folding -----------------
__global__ void prep_kernel(const float* __restrict__ Wq, const float* __restrict__ Wk,
                            const float* __restrict__ Wv, const float* __restrict__ Wo,
                            const float* __restrict__ Wc1, const float* __restrict__ Wc2,
                            const float* __restrict__ bc1) {
    int blk = blockIdx.x, tid = threadIdx.x;
    if (blk < 25) {
        // Weff[j][c][t] = sum_o Wc2[j][o] * Wc1[o][c][t], one tap t per block
        int t = blk;
        int j = tid >> 7, c = tid & 127;          // 256 threads = 2*128 outputs
        float s = 0.f;
        for (int o = 0; o < 128; o++)
            s += Wc2[j*128 + o] * Wc1[((size_t)(o*128 + c))*25 + t];
        g_Weff[(j*128 + c)*25 + t] = s;
    } else if (blk < 29) {
        const float* src = (blk==25) ? Wq : (blk==26) ? Wk : (blk==27) ? Wv : Wo;
        float*       dst = (blk==25) ? g_WqT : (blk==26) ? g_WkT : (blk==27) ? g_WvT : g_WoT;
        for (int idx = tid; idx < Cn*Cn; idx += 256) {
            int co = idx >> 7, ci = idx & 127;
            dst[ci*128 + co] = src[idx];
        }
    } else {
        if (tid < 2) {
            float s = 0.f;
            for (int o = 0; o < 128; o++) s += Wc2[tid*128 + o] * bc1[o];
            g_beff[tid] = s;
        }
    }
}

// ----------------- shared GEMM building blocks -----------------
__device__ __forceinline__ void copy16k(float* dst, const float* src, int tid) {
#pragma unroll
    for (int i = 0; i < 16; i++) {
        int idx = (i*256 + tid) * 4;
        *(float4*)(dst + idx) = *(const float4*)(src + idx);
    }
}

// C[m][n] += sum_k As[m*128+k] * Bs[k*128+n]; 8x8 per thread, 16x16 threads
__device__ __forceinline__ void gemm128(const float* __restrict__ As,
                                        const float* __restrict__ Bs,
                                        float acc[8][8], int m0, int n0) {
#pragma unroll 1
    for (int k = 0; k < 128; k += 4) {
        float4 a[8];
#pragma unroll
        for (int i = 0; i < 8; i++)
            a[i] = *(const float4*)(As + (m0 + i)*128 + k);
#pragma unroll
        for (int kk = 0; kk < 4; kk++) {
            float4 b0 = *(const float4*)(Bs + (k + kk)*128 + n0);
            float4 b1 = *(const float4*)(Bs + (k + kk)*128 + n0 + 4);
#pragma unroll
            for (int i = 0; i < 8; i++) {
                float av = (kk == 0) ? a[i].x : (kk == 1) ? a[i].y : (kk == 2) ? a[i].z : a[i].w;
                acc[i][0] += av*b0.x; acc[i][1] += av*b0.y;
                acc[i][2] += av*b0.z; acc[i][3] += av*b0.w;
                acc[i][4] += av*b1.x; acc[i][5] += av*b1.y;
                acc[i][6] += av*b1.z; acc[i][7] += av*b1.w;
            }
        }
    }
}

// ----------------- q projection: q[b,c,h,w] = Wq @ x + bq -----------------
__global__ void __launch_bounds__(256) qproj_kernel(const float* __restrict__ x,
                                                    const float* __restrict__ bq) {
    float* As = smem; float* Bs = smem + 16384;
    int tid = threadIdx.x;
    int b = blockIdx.x >> 7, h = blockIdx.x & 127;
    copy16k(As, x + ((size_t)(b*Hn + h))*Wn*Cn, tid);   // As[w][cin]
    copy16k(Bs, g_WqT, tid);                            // Bs[cin][cout]
    __syncthreads();
    int ty = tid >> 4, tx = tid & 15;
    float acc[8][8] = {};
    gemm128(As, Bs, acc, ty*8, tx*8);
#pragma unroll
    for (int j = 0; j < 8; j++) {
        int c = tx*8 + j;
        float bias = bq[c];
        float* dst = g_q + ((size_t)((b*Cn + c)*Hn + h))*Wn + ty*8;
        *(float4*)(dst)     = make_float4(acc[0][j]+bias, acc[1][j]+bias, acc[2][j]+bias, acc[3][j]+bias);
        *(float4*)(dst + 4) = make_float4(acc[4][j]+bias, acc[5][j]+bias, acc[6][j]+bias, acc[7][j]+bias);
    }
}

// ----------------- folded offset conv + sampling coordinates -----------------
__global__ void __launch_bounds__(256) offset_kernel() {
    __shared__ float tile[8*20*20];   // 8 channels, 20x20 halo tile
    __shared__ float wsm[2*8*25];
    int tid = threadIdx.x;
    int ty = tid >> 4, tx = tid & 15;
    int b  = blockIdx.x >> 6;
    int t8 = blockIdx.x & 63;
    int h0 = (t8 >> 3) * 16, w0 = (t8 & 7) * 16;
    float acc0 = g_beff[0], acc1 = g_beff[1];
    for (int c0 = 0; c0 < 128; c0 += 8) {
        __syncthreads();
        for (int idx = tid; idx < 3200; idx += 256) {
            int cc = idx / 400, rem = idx % 400;
            int r = rem / 20, col = rem % 20;
            int hh = h0 - 2 + r, ww = w0 - 2 + col;
            float v = 0.f;
            if (hh >= 0 && hh < Hn && ww >= 0 && ww < Wn)
                v = g_q[((size_t)((b*Cn + c0 + cc)*Hn + hh))*Wn + ww];
            tile[idx] = v;
        }
        for (int idx = tid; idx < 400; idx += 256) {
            int j = idx / 200, rem = idx % 200;
            int cc = rem / 25, t = rem % 25;
            wsm[idx] = g_Weff[((j*128) + c0 + cc)*25 + t];
        }
        __syncthreads();
#pragma unroll
        for (int cc = 0; cc < 8; cc++) {
#pragma unroll
            for (int kh = 0; kh < 5; kh++) {
#pragma unroll
                for (int kw = 0; kw < 5; kw++) {
                    float v = tile[cc*400 + (ty + kh)*20 + tx + kw];
                    acc0 += v * wsm[      cc*25 + kh*5 + kw];
                    acc1 += v * wsm[200 + cc*25 + kh*5 + kw];
                }
            }
        }
    }
    float off0 = tanhf(acc0) * 5.f;
    float off1 = tanhf(acc1) * 5.f;
    int h = h0 + ty, w = w0 + tx;
    // x-coord from offset ch0 (normalized by H-1), y from ch1 (by W-1); H==W==128
    float xg = ((float)w + off0) * (128.f/127.f) - 0.5f;
    float yg = ((float)h + off1) * (128.f/127.f) - 0.5f;
    size_t p = ((size_t)(b*Hn + h))*Wn + w;
    g_coords[p*2]   = xg;
    g_coords[p*2+1] = yg;
}

// ----------------- bilinear gather (zero padding, align_corners=False) -----------------
__global__ void __launch_bounds__(256) sample_kernel(const float* __restrict__ x) {
    int tid = threadIdx.x;
    int lane = tid & 31, wa = tid >> 5;
    int b = blockIdx.x >> 7, h = blockIdx.x & 127;
    const float* xb = x + (size_t)b*Hn*Wn*Cn;
    for (int w = wa; w < Wn; w += 8) {
        size_t p = ((size_t)(b*Hn + h))*Wn + w;
        float xg = g_coords[2*p], yg = g_coords[2*p + 1];
        float x0 = floorf(xg), y0 = floorf(yg);
        float4 out = make_float4(0.f, 0.f, 0.f, 0.f);
#pragma unroll
        for (int dy = 0; dy < 2; dy++) {
#pragma unroll
            for (int dx = 0; dx < 2; dx++) {
                float xi = x0 + (float)dx, yi = y0 + (float)dy;
                float wt = (1.f - fabsf(xg - xi)) * (1.f - fabsf(yg - yi));
                bool valid = (xi >= 0.f) && (xi <= 127.f) && (yi >= 0.f) && (yi <= 127.f);
                float wv = valid ? wt : 0.f;
                int ix = min(max((int)xi, 0), 127);
                int iy = min(max((int)yi, 0), 127);
                float4 src = *(const float4*)(xb + ((size_t)(iy*Wn + ix))*Cn + lane*4);
                out.x += wv*src.x; out.y += wv*src.y; out.z += wv*src.z; out.w += wv*src.w;
            }
        }
        *(float4*)(g_xs + p*Cn + lane*4) = out;
    }
}

// ----------------- k projection, written transposed: kT[b,c,w,h] -----------------
__global__ void __launch_bounds__(256) kproj_kernel(const float* __restrict__ bk) {
    float* As = smem; float* Bs = smem + 16384;
    int tid = threadIdx.x;
    int b = blockIdx.x >> 7, w = blockIdx.x & 127;
    // As[h][cin] = xs[b,h,w,:]
#pragma unroll
    for (int i = 0; i < 16; i++) {
        int idx = i*256 + tid;           // float4 index (4096 total)
        int hh = idx >> 5, c4 = idx & 31;
        *(float4*)(As + hh*128 + c4*4) =
            *(const float4*)(g_xs + ((size_t)((b*Hn + hh)*Wn + w))*Cn + c4*4);
    }
    copy16k(Bs, g_WkT, tid);
    __syncthreads();
    int ty = tid >> 4, tx = tid & 15;
    float acc[8][8] = {};
    gemm128(As, Bs, acc, ty*8, tx*8);    // out[h][cout]
#pragma unroll
    for (int j = 0; j < 8; j++) {
        int c = tx*8 + j;
        float bias = bk[c];
        float* dst = g_kT + ((size_t)((b*Cn + c)*Wn + w))*Hn + ty*8;
        *(float4*)(dst)     = make_float4(acc[0][j]+bias, acc[1][j]+bias, acc[2][j]+bias, acc[3][j]+bias);
        *(float4*)(dst + 4) = make_float4(acc[4][j]+bias, acc[5][j]+bias, acc[6][j]+bias, acc[7][j]+bias);
    }
}

// ----------------- v projection (natural layout) + rel_bias -----------------
__global__ void __launch_bounds__(256) vproj_kernel(const float* __restrict__ bv,
                                                    const float* __restrict__ rel_bias) {
    float* As = smem; float* Bs = smem + 16384;
    int tid = threadIdx.x;
    int b = blockIdx.x >> 7, h = blockIdx.x & 127;
    copy16k(As, g_xs + ((size_t)(b*Hn + h))*Wn*Cn, tid);   // As[w][cin]
    copy16k(Bs, g_WvT, tid);
    __syncthreads();
    int ty = tid >> 4, tx = tid & 15;
    float acc[8][8] = {};
    gemm128(As, Bs, acc, ty*8, tx*8);    // out[w][cout]
#pragma unroll
    for (int j = 0; j < 8; j++) {
        int c = tx*8 + j;
        float bias = bv[c] + rel_bias[c*Hn + h];
        float* dst = g_v + ((size_t)((b*Cn + c)*Hn + h))*Wn + ty*8;
        *(float4*)(dst)     = make_float4(acc[0][j]+bias, acc[1][j]+bias, acc[2][j]+bias, acc[3][j]+bias);
        *(float4*)(dst + 4) = make_float4(acc[4][j]+bias, acc[5][j]+bias, acc[6][j]+bias, acc[7][j]+bias);
    }
}

// ----------------- attention: one (b,c) slice per block -----------------
__global__ void __launch_bounds__(256) attn_kernel() {
    float* qs = smem;               // [i][d], later reused as attn[i][j]
    float* ks = smem + 16384;       // [d][j]  (k transposed on disk)
    float* vs = smem + 32768;       // [j][d]
    int s = blockIdx.x, tid = threadIdx.x;
    copy16k(qs, g_q  + (size_t)s*SLICE, tid);
    copy16k(ks, g_kT + (size_t)s*SLICE, tid);
    copy16k(vs, g_v  + (size_t)s*SLICE, tid);
    __syncthreads();
    int ty = tid >> 4, tx = tid & 15;
    int m0 = ty*8, n0 = tx*8;

    float acc[8][8] = {};
    gemm128(qs, ks, acc, m0, n0);   // raw scores (unscaled)

    // softmax over j of (scale * scores); rows owned by 16-lane groups
#pragma unroll
    for (int i = 0; i < 8; i++) {
        float m = acc[i][0];
#pragma unroll
        for (int j = 1; j < 8; j++) m = fmaxf(m, acc[i][j]);
#pragma unroll
        for (int off = 8; off > 0; off >>= 1)
            m = fmaxf(m, __shfl_xor_sync(0xffffffffu, m, off));
        float sum = 0.f;
#pragma unroll
        for (int j = 0; j < 8; j++) {
            float p = expf((acc[i][j] - m) * ATT_SCALE);
            acc[i][j] = p;
            sum += p;
        }
#pragma unroll
        for (int off = 8; off > 0; off >>= 1)
            sum += __shfl_xor_sync(0xffffffffu, sum, off);
        float inv = 1.f / sum;
#pragma unroll
        for (int j = 0; j < 8; j++) acc[i][j] *= inv;
    }

    __syncthreads();                // all GEMM1 reads of qs done
#pragma unroll
    for (int i = 0; i < 8; i++) {
        *(float4*)(qs + (m0+i)*128 + n0)     = make_float4(acc[i][0], acc[i][1], acc[i][2], acc[i][3]);
        *(float4*)(qs + (m0+i)*128 + n0 + 4) = make_float4(acc[i][4], acc[i][5], acc[i][6], acc[i][7]);
    }
    __syncthreads();

    float acc2[8][8] = {};
    gemm128(qs, vs, acc2, m0, n0);  // out[i][d]
    float* dst = g_ao + (size_t)s*SLICE;
#pragma unroll
    for (int i = 0; i < 8; i++) {
        *(float4*)(dst + (m0+i)*128 + n0)     = make_float4(acc2[i][0], acc2[i][1], acc2[i][2], acc2[i][3]);
        *(float4*)(dst + (m0+i)*128 + n0 + 4) = make_float4(acc2[i][4], acc2[i][5], acc2[i][6], acc2[i][7]);
    }
}

// ----------------- output projection (raw reshape == flat (N,C) GEMM) -----------------
__global__ void __launch_bounds__(256) oproj_kernel(float* __restrict__ out,
                                                    const float* __restrict__ bo) {
    float* As = smem; float* Bs = smem + 16384;
    int tid = threadIdx.x;
    copy16k(As, g_ao + (size_t)blockIdx.x*16384, tid);   // As[m][c] (flat view)
    copy16k(Bs, g_WoT, tid);
    __syncthreads();
    int ty = tid >> 4, tx = tid & 15;
    float acc[8][8] = {};
    gemm128(As, Bs, acc, ty*8, tx*8);
    float bias[8];
#pragma unroll
    for (int j = 0; j < 8; j++) bias[j] = bo[tx*8 + j];
    float* dst = out + (size_t)blockIdx.x*16384;
#pragma unroll
    for (int i = 0; i < 8; i++) {
        *(float4*)(dst + (ty*8+i)*128 + tx*8)     = make_float4(acc[i][0]+bias[0], acc[i][1]+bias[1],
                                                                acc[i][2]+bias[2], acc[i][3]+bias[3]);
        *(float4*)(dst + (ty*8+i)*128 + tx*8 + 4) = make_float4(acc[i][4]+bias[4], acc[i][5]+bias[5],
                                                                acc[i][6]+bias[6], acc[i][7]+bias[7]);
    }
}

// ----------------- launch -----------------
extern "C" void kernel_launch(void* const* d_in, const int* in_sizes, int n_in,
                              void* d_out, int out_size) {
    const float* x   = (const float*)d_in[0];
    // d_in[1] = cycle_index (dead path)
    const float* Wq  = (const float*)d_in[2];
    const float* bq  = (const float*)d_in[3];
    const float* Wk  = (const float*)d_in[4];
    const float* bk  = (const float*)d_in[5];
    const float* Wv  = (const float*)d_in[6];
    const float* bv  = (const float*)d_in[7];
    const float* Wo  = (const float*)d_in[8];
    const float* bo  = (const float*)d_in[9];
    const float* Wc1 = (const float*)d_in[10];
    const float* bc1 = (const float*)d_in[11];
    const float* Wc2 = (const float*)d_in[12];
    const float* rb  = (const float*)d_in[13];
    float* out = (float*)d_out;

    cudaFuncSetAttribute(qproj_kernel, cudaFuncAttributeMaxDynamicSharedMemorySize, 131072);
    cudaFuncSetAttribute(kproj_kernel, cudaFuncAttributeMaxDynamicSharedMemorySize, 131072);
    cudaFuncSetAttribute(vproj_kernel, cudaFuncAttributeMaxDynamicSharedMemorySize, 131072);
    cudaFuncSetAttribute(oproj_kernel, cudaFuncAttributeMaxDynamicSharedMemorySize, 131072);
    cudaFuncSetAttribute(attn_kernel,  cudaFuncAttributeMaxDynamicSharedMemorySize, 196608);

    prep_kernel  <<<30,  256>>>(Wq, Wk, Wv, Wo, Wc1, Wc2, bc1);
    qproj_kernel <<<512, 256, 131072>>>(x, bq);
    offset_kernel<<<256, 256>>>();
    sample_kernel<<<512, 256>>>(x);
    kproj_kernel <<<512, 256, 131072>>>(bk);
    vproj_kernel <<<512, 256, 131072>>>(bv, rb);
    attn_kernel  <<<512, 256, 196608>>>();
    oproj_kernel <<<512, 256, 131072>>>(out, bo);
}

// round 2
// speedup vs baseline: 1.1026x; 1.1026x over previous
#include <cuda_runtime.h>
#include <math.h>

#define Bn 4
#define Hn 128
#define Wn 128
#define Cn 128
#define SLICE (Hn*Wn)              // 16384
#define NPOS (Bn*Hn*Wn)            // 65536
#define ATT_SCALE 0.08838834764831845f   // 128^-0.5

#define LDA 68        // padded ld for [row][k] chunk arrays (bank = g*4+t, conflict-free)
#define LDV 136       // padded ld for [k][n] V-style arrays (bank = t*8+g, conflict-free)
#define SMEM_BYTES 139264   // 4 * 8704 floats

// ----------------- scratch (device globals; no allocations) -----------------
__device__ __align__(128) float g_q [Bn*Cn*SLICE];   // (B,C,H,W)
__device__ __align__(128) float g_k [Bn*Cn*SLICE];   // (B,C,H,W)
__device__ __align__(128) float g_v [Bn*Cn*SLICE];   // (B,C,H,W)
__device__ __align__(128) float g_xs[NPOS*Cn];       // (B,H,W,C) sampled
__device__ __align__(128) float g_coords[NPOS*2];
__device__ __align__(128) float g_Weff[2*Cn*25];     // folded Wc2 @ Wc1
__device__ __align__(128) float g_beff[2];

extern __shared__ float smem[];

// ----------------- tf32 helpers -----------------
__device__ __forceinline__ unsigned f2tf(float x) {
    unsigned r; asm("cvt.rna.tf32.f32 %0, %1;" : "=r"(r) : "f"(x)); return r;
}
struct HL { unsigned h, l; };
__device__ __forceinline__ HL cvt_hl(float x) {
    HL o; o.h = f2tf(x);
    o.l = f2tf(x - __uint_as_float(o.h));
    return o;
}
__device__ __forceinline__ void mma8(float c[4], const unsigned a[4], unsigned b0, unsigned b1) {
    asm volatile(
        "mma.sync.aligned.m16n8k8.row.col.f32.tf32.tf32.f32 "
        "{%0,%1,%2,%3},{%4,%5,%6,%7},{%8,%9},{%0,%1,%2,%3};"
        : "+f"(c[0]), "+f"(c[1]), "+f"(c[2]), "+f"(c[3])
        : "r"(a[0]), "r"(a[1]), "r"(a[2]), "r"(a[3]), "r"(b0), "r"(b1));
}

// ----------------- smem chunk loaders (fp32 -> hi/lo tf32) -----------------
// 128 rows x 64 cols, row-major source (stride ld), into [row][64] with LDA pad
__device__ __forceinline__ void load_rm_128x64(const float* __restrict__ src, int ld,
                                               float* sh, float* sl, int tid, float mul) {
#pragma unroll
    for (int it = 0; it < 8; it++) {
        int idx = it*256 + tid;
        int r = idx >> 4, f4 = idx & 15;
        float4 v = *(const float4*)(src + (size_t)r*ld + f4*4);
        uint4 h, l; HL a;
        a = cvt_hl(v.x*mul); h.x = a.h; l.x = a.l;
        a = cvt_hl(v.y*mul); h.y = a.h; l.y = a.l;
        a = cvt_hl(v.z*mul); h.z = a.h; l.z = a.l;
        a = cvt_hl(v.w*mul); h.w = a.h; l.w = a.l;
        *(uint4*)(sh + r*LDA + f4*4) = h;
        *(uint4*)(sl + r*LDA + f4*4) = l;
    }
}
// 64 rows x 128 cols (V-style [k][n]), into LDV-padded arrays
__device__ __forceinline__ void load_rm_64x128_v(const float* __restrict__ src, int ld,
                                                 float* sh, float* sl, int tid) {
#pragma unroll
    for (int it = 0; it < 8; it++) {
        int idx = it*256 + tid;
        int r = idx >> 5, f4 = idx & 31;
        float4 v = *(const float4*)(src + (size_t)r*ld + f4*4);
        uint4 h, l; HL a;
        a = cvt_hl(v.x); h.x = a.h; l.x = a.l;
        a = cvt_hl(v.y); h.y = a.h; l.y = a.l;
        a = cvt_hl(v.z); h.z = a.h; l.z = a.l;
        a = cvt_hl(v.w); h.w = a.h; l.w = a.l;
        *(uint4*)(sh + r*LDV + f4*4) = h;
        *(uint4*)(sl + r*LDV + f4*4) = l;
    }
}

// ----------------- tf32x3 GEMM over one K=64 chunk -----------------
// MT m16-tiles, NT n8-tiles per warp. B either W-style [n][k] (LDA) or V-style [k][n] (LDV).
template<int MT, int NT, bool VSTYLE>
__device__ __forceinline__ void gemm_chunk(const float* sAh, const float* sAl,
                                           const float* sBh, const float* sBl,
                                           float (*acc)[NT][4], int m0, int n0, int g, int t) {
#pragma unroll
    for (int ks = 0; ks < 8; ks++) {
        int k0 = ks*8;
        unsigned ah[MT][4], al[MT][4];
#pragma unroll
        for (int mt = 0; mt < MT; mt++) {
            int ra = (m0 + mt*16 + g)*LDA + k0 + t;
            ah[mt][0] = __float_as_uint(sAh[ra]);
            ah[mt][1] = __float_as_uint(sAh[ra + 8*LDA]);
            ah[mt][2] = __float_as_uint(sAh[ra + 4]);
            ah[mt][3] = __float_as_uint(sAh[ra + 8*LDA + 4]);
            al[mt][0] = __float_as_uint(sAl[ra]);
            al[mt][1] = __float_as_uint(sAl[ra + 8*LDA]);
            al[mt][2] = __float_as_uint(sAl[ra + 4]);
            al[mt][3] = __float_as_uint(sAl[ra + 8*LDA + 4]);
        }
#pragma unroll
        for (int nt = 0; nt < NT; nt++) {
            unsigned bh0, bh1, bl0, bl1;
            if (VSTYLE) {
                int rb = (k0 + t)*LDV + n0 + nt*8 + g;
                bh0 = __float_as_uint(sBh[rb]); bh1 = __float_as_uint(sBh[rb + 4*LDV]);
                bl0 = __float_as_uint(sBl[rb]); bl1 = __float_as_uint(sBl[rb + 4*LDV]);
            } else {
                int rb = (n0 + nt*8 + g)*LDA + k0 + t;
                bh0 = __float_as_uint(sBh[rb]); bh1 = __float_as_uint(sBh[rb + 4]);
                bl0 = __float_as_uint(sBl[rb]); bl1 = __float_as_uint(sBl[rb + 4]);
            }
#pragma unroll
            for (int mt = 0; mt < MT; mt++) {
                mma8(acc[mt][nt], ah[mt], bh0, bh1);
                mma8(acc[mt][nt], ah[mt], bl0, bl1);
                mma8(acc[mt][nt], al[mt], bh0, bh1);
            }
        }
    }
}

// ----------------- prep: conv folding -----------------
__global__ void prep_kernel(const float* __restrict__ Wc1, const float* __restrict__ Wc2,
                            const float* __restrict__ bc1) {
    int blk = blockIdx.x, tid = threadIdx.x;
    if (blk < 25) {
        int t = blk;
        int j = tid >> 7, c = tid & 127;
        float s = 0.f;
        for (int o = 0; o < 128; o++)
            s += Wc2[j*128 + o] * Wc1[((size_t)(o*128 + c))*25 + t];
        g_Weff[(j*128 + c)*25 + t] = s;
    } else {
        if (tid < 2) {
            float s = 0.f;
            for (int o = 0; o < 128; o++) s += Wc2[tid*128 + o] * bc1[o];
            g_beff[tid] = s;
        }
    }
}

// ----------------- projection: out[b,c,h,w] = W @ src + bias (+rel) -----------------
__global__ void __launch_bounds__(256,1) proj_kernel(const float* __restrict__ x, int use_xs,
                                                     const float* __restrict__ W,
                                                     const float* __restrict__ bias,
                                                     const float* __restrict__ rel, int dst_sel) {
    float *sAh = smem, *sAl = smem + 8704, *sBh = smem + 17408, *sBl = smem + 26112;
    int tid = threadIdx.x, wid = tid >> 5, lane = tid & 31, g = lane >> 2, t = lane & 3;
    int b = blockIdx.x >> 7, h = blockIdx.x & 127;
    const float* src = (use_xs ? g_xs : x) + ((size_t)(b*128 + h))*128*128;  // [w][cin]

    float acc[2][8][4] = {};
    int m0 = (wid >> 1)*32, n0 = (wid & 1)*64;
    for (int kc = 0; kc < 2; kc++) {
        load_rm_128x64(src + kc*64, 128, sAh, sAl, tid, 1.f);
        load_rm_128x64(W   + kc*64, 128, sBh, sBl, tid, 1.f);
        __syncthreads();
        gemm_chunk<2,8,false>(sAh, sAl, sBh, sBl, acc, m0, n0, g, t);
        __syncthreads();
    }
    // stage transposed [c][w] (ld 132, conflict-free writes)
    float* stage = smem;
#pragma unroll
    for (int mt = 0; mt < 2; mt++)
#pragma unroll
        for (int nt = 0; nt < 8; nt++) {
            int m = m0 + mt*16 + g, c = n0 + nt*8 + 2*t;
            stage[c*132 + m]         = acc[mt][nt][0];
            stage[(c+1)*132 + m]     = acc[mt][nt][1];
            stage[c*132 + m + 8]     = acc[mt][nt][2];
            stage[(c+1)*132 + m + 8] = acc[mt][nt][3];
        }
    __syncthreads();
    float* dst = (dst_sel == 0 ? g_q : dst_sel == 1 ? g_k : g_v)
                 + ((size_t)b*128)*16384 + h*128;
#pragma unroll
    for (int it = 0; it < 16; it++) {
        int idx = it*256 + tid;
        int c = idx >> 5, w4 = idx & 31;
        float bv = bias[c] + (rel ? rel[c*128 + h] : 0.f);
        float4 v = *(float4*)(stage + c*132 + w4*4);
        v.x += bv; v.y += bv; v.z += bv; v.w += bv;
        *(float4*)(dst + (size_t)c*16384 + w4*4) = v;
    }
}

// ----------------- folded offset conv + sampling coordinates -----------------
__global__ void __launch_bounds__(256) offset_kernel() {
    __shared__ float tile[8*20*20];
    __shared__ float wsm[2*8*25];
    int tid = threadIdx.x;
    int ty = tid >> 4, tx = tid & 15;
    int b  = blockIdx.x >> 6;
    int t8 = blockIdx.x & 63;
    int h0 = (t8 >> 3)*16, w0 = (t8 & 7)*16;
    float acc0 = g_beff[0], acc1 = g_beff[1];
    for (int c0 = 0; c0 < 128; c0 += 8) {
        __syncthreads();
        for (int idx = tid; idx < 3200; idx += 256) {
            int cc = idx / 400, rem = idx % 400;
            int r = rem / 20, col = rem % 20;
            int hh = h0 - 2 + r, ww = w0 - 2 + col;
            float v = 0.f;
            if (hh >= 0 && hh < Hn && ww >= 0 && ww < Wn)
                v = g_q[((size_t)((b*Cn + c0 + cc)*Hn + hh))*Wn + ww];
            tile[idx] = v;
        }
        for (int idx = tid; idx < 400; idx += 256) {
            int j = idx / 200, rem = idx % 200;
            int cc = rem / 25, t = rem % 25;
            wsm[idx] = g_Weff[((j*128) + c0 + cc)*25 + t];
        }
        __syncthreads();
#pragma unroll
        for (int cc = 0; cc < 8; cc++)
#pragma unroll
            for (int kh = 0; kh < 5; kh++)
#pragma unroll
                for (int kw = 0; kw < 5; kw++) {
                    float v = tile[cc*400 + (ty + kh)*20 + tx + kw];
                    acc0 += v * wsm[      cc*25 + kh*5 + kw];
                    acc1 += v * wsm[200 + cc*25 + kh*5 + kw];
                }
    }
    float off0 = tanhf(acc0)*5.f;
    float off1 = tanhf(acc1)*5.f;
    int h = h0 + ty, w = w0 + tx;
    float xg = ((float)w + off0)*(128.f/127.f) - 0.5f;
    float yg = ((float)h + off1)*(128.f/127.f) - 0.5f;
    size_t p = ((size_t)(b*Hn + h))*Wn + w;
    g_coords[p*2]   = xg;
    g_coords[p*2+1] = yg;
}

// ----------------- bilinear gather -----------------
__global__ void __launch_bounds__(256) sample_kernel(const float* __restrict__ x) {
    int tid = threadIdx.x;
    int lane = tid & 31, wa = tid >> 5;
    int b = blockIdx.x >> 7, h = blockIdx.x & 127;
    const float* xb = x + (size_t)b*Hn*Wn*Cn;
    for (int w = wa; w < Wn; w += 8) {
        size_t p = ((size_t)(b*Hn + h))*Wn + w;
        float xg = g_coords[2*p], yg = g_coords[2*p + 1];
        float x0 = floorf(xg), y0 = floorf(yg);
        float4 out = make_float4(0.f, 0.f, 0.f, 0.f);
#pragma unroll
        for (int dy = 0; dy < 2; dy++)
#pragma unroll
            for (int dx = 0; dx < 2; dx++) {
                float xi = x0 + (float)dx, yi = y0 + (float)dy;
                float wt = (1.f - fabsf(xg - xi))*(1.f - fabsf(yg - yi));
                bool valid = (xi >= 0.f) && (xi <= 127.f) && (yi >= 0.f) && (yi <= 127.f);
                float wv = valid ? wt : 0.f;
                int ix = min(max((int)xi, 0), 127);
                int iy = min(max((int)yi, 0), 127);
                float4 src = *(const float4*)(xb + ((size_t)(iy*Wn + ix))*Cn + lane*4);
                out.x += wv*src.x; out.y += wv*src.y; out.z += wv*src.z; out.w += wv*src.w;
            }
        *(float4*)(g_xs + p*Cn + lane*4) = out;
    }
}

// ----------------- attention + fused output projection -----------------
__global__ void __launch_bounds__(256,1) attn_kernel(const float* __restrict__ Wo,
                                                     const float* __restrict__ bo,
                                                     float* __restrict__ out) {
    float *sAh = smem, *sAl = smem + 8704, *sBh = smem + 17408, *sBl = smem + 26112;
    int tid = threadIdx.x, wid = tid >> 5, lane = tid & 31, g = lane >> 2, t = lane & 3;
    int s = blockIdx.x;
    const float* qsl = g_q + (size_t)s*SLICE;
    const float* ksl = g_k + (size_t)s*SLICE;
    const float* vsl = g_v + (size_t)s*SLICE;

    // ---- scores = (q*scale) @ k^T : warp tile 16x128 (full rows per warp) ----
    float sacc[1][16][4] = {};
    int m0s = wid*16;
    for (int kc = 0; kc < 2; kc++) {
        load_rm_128x64(qsl + kc*64, 128, sAh, sAl, tid, ATT_SCALE);
        load_rm_128x64(ksl + kc*64, 128, sBh, sBl, tid, 1.f);
        __syncthreads();
        gemm_chunk<1,16,false>(sAh, sAl, sBh, sBl, sacc, m0s, 0, g, t);
        __syncthreads();
    }

    // ---- softmax: rows m0s+g and m0s+g+8, reduce over t-group (xor 1,2) ----
    float mx0 = -1e30f, mx1 = -1e30f;
#pragma unroll
    for (int nt = 0; nt < 16; nt++) {
        mx0 = fmaxf(mx0, fmaxf(sacc[0][nt][0], sacc[0][nt][1]));
        mx1 = fmaxf(mx1, fmaxf(sacc[0][nt][2], sacc[0][nt][3]));
    }
    mx0 = fmaxf(mx0, __shfl_xor_sync(~0u, mx0, 1));
    mx0 = fmaxf(mx0, __shfl_xor_sync(~0u, mx0, 2));
    mx1 = fmaxf(mx1, __shfl_xor_sync(~0u, mx1, 1));
    mx1 = fmaxf(mx1, __shfl_xor_sync(~0u, mx1, 2));
    float s0 = 0.f, s1 = 0.f;
#pragma unroll
    for (int nt = 0; nt < 16; nt++) {
        float p0 = expf(sacc[0][nt][0] - mx0); sacc[0][nt][0] = p0; s0 += p0;
        float p1 = expf(sacc[0][nt][1] - mx0); sacc[0][nt][1] = p1; s0 += p1;
        float p2 = expf(sacc[0][nt][2] - mx1); sacc[0][nt][2] = p2; s1 += p2;
        float p3 = expf(sacc[0][nt][3] - mx1); sacc[0][nt][3] = p3; s1 += p3;
    }
    s0 += __shfl_xor_sync(~0u, s0, 1); s0 += __shfl_xor_sync(~0u, s0, 2);
    s1 += __shfl_xor_sync(~0u, s1, 1); s1 += __shfl_xor_sync(~0u, s1, 2);
    float inv0 = 1.f/s0, inv1 = 1.f/s1;

    // ---- PV: warp tile 32x64 ----
    float vacc[2][8][4] = {};
    int m0 = (wid >> 1)*32, n0 = (wid & 1)*64;
    for (int kc = 0; kc < 2; kc++) {
        // store P chunk (cols kc*64..kc*64+63) into A buffers as hi/lo
        int r0 = m0s + g;
#pragma unroll
        for (int nt = kc*8; nt < kc*8 + 8; nt++) {
            int jc = nt*8 - kc*64 + 2*t;
            HL a;
            a = cvt_hl(sacc[0][nt][0]*inv0);
            sAh[r0*LDA + jc]     = __uint_as_float(a.h); sAl[r0*LDA + jc]     = __uint_as_float(a.l);
            a = cvt_hl(sacc[0][nt][1]*inv0);
            sAh[r0*LDA + jc + 1] = __uint_as_float(a.h); sAl[r0*LDA + jc + 1] = __uint_as_float(a.l);
            a = cvt_hl(sacc[0][nt][2]*inv1);
            sAh[(r0+8)*LDA + jc]     = __uint_as_float(a.h); sAl[(r0+8)*LDA + jc]     = __uint_as_float(a.l);
            a = cvt_hl(sacc[0][nt][3]*inv1);
            sAh[(r0+8)*LDA + jc + 1] = __uint_as_float(a.h); sAl[(r0+8)*LDA + jc + 1] = __uint_as_float(a.l);
        }
        load_rm_64x128_v(vsl + (size_t)kc*64*128, 128, sBh, sBl, tid);
        __syncthreads();
        gemm_chunk<2,8,true>(sAh, sAl, sBh, sBl, vacc, m0, n0, g, t);
        __syncthreads();
    }

    // ---- O = PV @ Wo^T (fused output projection) ----
    float oacc[2][8][4] = {};
    for (int kc = 0; kc < 2; kc++) {
        if ((wid & 1) == kc) {   // warps owning d-chunk kc store PV into A buffers
#pragma unroll
            for (int mt = 0; mt < 2; mt++)
#pragma unroll
                for (int nt = 0; nt < 8; nt++) {
                    int m = m0 + mt*16 + g, jc = nt*8 + 2*t;
                    HL a;
                    a = cvt_hl(vacc[mt][nt][0]);
                    sAh[m*LDA + jc]     = __uint_as_float(a.h); sAl[m*LDA + jc]     = __uint_as_float(a.l);
                    a = cvt_hl(vacc[mt][nt][1]);
                    sAh[m*LDA + jc + 1] = __uint_as_float(a.h); sAl[m*LDA + jc + 1] = __uint_as_float(a.l);
                    a = cvt_hl(vacc[mt][nt][2]);
                    sAh[(m+8)*LDA + jc]     = __uint_as_float(a.h); sAl[(m+8)*LDA + jc]     = __uint_as_float(a.l);
                    a = cvt_hl(vacc[mt][nt][3]);
                    sAh[(m+8)*LDA + jc + 1] = __uint_as_float(a.h); sAl[(m+8)*LDA + jc + 1] = __uint_as_float(a.l);
                }
        }
        load_rm_128x64(Wo + kc*64, 128, sBh, sBl, tid, 1.f);
        __syncthreads();
        gemm_chunk<2,8,false>(sAh, sAl, sBh, sBl, oacc, m0, n0, g, t);
        __syncthreads();
    }

    // ---- epilogue: out[(s*128 + i)*128 + c] = oacc + bo ----
    float* ob = out + (size_t)s*SLICE;
#pragma unroll
    for (int mt = 0; mt < 2; mt++)
#pragma unroll
        for (int nt = 0; nt < 8; nt++) {
            int m = m0 + mt*16 + g, n = n0 + nt*8 + 2*t;
            float b0 = bo[n], b1 = bo[n+1];
            *(float2*)(ob + m*128 + n)     = make_float2(oacc[mt][nt][0] + b0, oacc[mt][nt][1] + b1);
            *(float2*)(ob + (m+8)*128 + n) = make_float2(oacc[mt][nt][2] + b0, oacc[mt][nt][3] + b1);
        }
}

// ----------------- launch -----------------
extern "C" void kernel_launch(void* const* d_in, const int* in_sizes, int n_in,
                              void* d_out, int out_size) {
    const float* x   = (const float*)d_in[0];
    const float* Wq  = (const float*)d_in[2];
    const float* bq  = (const float*)d_in[3];
    const float* Wk  = (const float*)d_in[4];
    const float* bk  = (const float*)d_in[5];
    const float* Wv  = (const float*)d_in[6];
    const float* bv  = (const float*)d_in[7];
    const float* Wo  = (const float*)d_in[8];
    const float* bo  = (const float*)d_in[9];
    const float* Wc1 = (const float*)d_in[10];
    const float* bc1 = (const float*)d_in[11];
    const float* Wc2 = (const float*)d_in[12];
    const float* rb  = (const float*)d_in[13];
    float* out = (float*)d_out;

    cudaFuncSetAttribute(proj_kernel, cudaFuncAttributeMaxDynamicSharedMemorySize, SMEM_BYTES);
    cudaFuncSetAttribute(attn_kernel, cudaFuncAttributeMaxDynamicSharedMemorySize, SMEM_BYTES);

    prep_kernel  <<<26,  256>>>(Wc1, Wc2, bc1);
    proj_kernel  <<<512, 256, SMEM_BYTES>>>(x, 0, Wq, bq, nullptr, 0);
    offset_kernel<<<256, 256>>>();
    sample_kernel<<<512, 256>>>(x);
    proj_kernel  <<<512, 256, SMEM_BYTES>>>(x, 1, Wk, bk, nullptr, 1);
    proj_kernel  <<<512, 256, SMEM_BYTES>>>(x, 1, Wv, bv, rb, 2);
    attn_kernel  <<<512, 256, SMEM_BYTES>>>(Wo, bo, out);
}